// round 5
// baseline (speedup 1.0000x reference)
#include <cuda_runtime.h>

#define NPTS 12288
#define DIM 16
#define KSPLIT 48
#define QBLK 128
#define QPT 4
#define QPB (QBLK * QPT)                // 512 queries per block
#define QTILES (NPTS / QPB)             // 24
#define KEYS_PER_SPLIT (NPTS / KSPLIT)  // 256
#define KTILE 256
#define SOP_BLK 256
#define SOP_BLOCKS (NPTS / SOP_BLK)     // 48

typedef unsigned long long u64;

// Scratch (no device allocation allowed -> __device__ globals)
__device__ float g_se[KSPLIT][NPTS];        // exp-sum partials
__device__ float g_sw[KSPLIT][NPTS];        // exp*score-sum partials (log2-units)
__device__ float g_Mpart[SOP_BLOCKS][256];  // per-block SOP partials

// ---- packed f32x2 helpers -------------------------------------------------
__device__ __forceinline__ u64 pack2(float lo, float hi) {
    u64 r; asm("mov.b64 %0, {%1, %2};" : "=l"(r) : "f"(lo), "f"(hi)); return r;
}
__device__ __forceinline__ void unpack2(u64 v, float& lo, float& hi) {
    asm("mov.b64 {%0, %1}, %2;" : "=f"(lo), "=f"(hi) : "l"(v));
}
__device__ __forceinline__ u64 fma2(u64 a, u64 b, u64 c) {
    u64 d; asm("fma.rn.f32x2 %0, %1, %2, %3;" : "=l"(d) : "l"(a), "l"(b), "l"(c)); return d;
}
__device__ __forceinline__ u64 mul2(u64 a, u64 b) {
    u64 d; asm("mul.rn.f32x2 %0, %1, %2;" : "=l"(d) : "l"(a), "l"(b)); return d;
}
__device__ __forceinline__ u64 add2(u64 a, u64 b) {
    u64 d; asm("add.rn.f32x2 %0, %1, %2;" : "=l"(d) : "l"(a), "l"(b)); return d;
}
__device__ __forceinline__ float ex2_approx(float x) {
    float r; asm("ex2.approx.ftz.f32 %0, %1;" : "=f"(r) : "f"(x)); return r;
}

// ---------------------------------------------------------------------------
// Kernel 1: attention row-statistics, split over keys, FOUR queries/thread.
// Identity: <ctx_q, f_q> = 4*ln2 * (sum_j e_j t_j)/(sum_j e_j) where
// t = score*log2(e). One key load (4x LDS.128) feeds four dot chains.
// se/sw accumulate as one packed fma2 per pair: acc += {e,e}*{1,t}.
// ---------------------------------------------------------------------------
__global__ void __launch_bounds__(QBLK, 5) attn_kernel(const float* __restrict__ feats) {
    __shared__ ulonglong2 sk[KTILE * 4];  // 256 keys x 16 floats = 16 KB

    const int tid   = threadIdx.x;
    const int qt    = blockIdx.x % QTILES;
    const int split = blockIdx.x / QTILES;
    const int qbase = qt * QPB + tid;

    // load 4 queries as packed f32x2, pre-scaled by 0.25 * log2(e)
    u64 qp[QPT][8];
    {
        const float sc = 0.25f * 1.4426950408889634f;
        const u64 s2 = pack2(sc, sc);
        #pragma unroll
        for (int u = 0; u < QPT; u++) {
            const ulonglong2* fq =
                reinterpret_cast<const ulonglong2*>(feats) + (qbase + u * QBLK) * 4;
            #pragma unroll
            for (int i = 0; i < 4; i++) {
                ulonglong2 v = fq[i];
                qp[u][2 * i + 0] = mul2(v.x, s2);
                qp[u][2 * i + 1] = mul2(v.y, s2);
            }
        }
    }

    u64 acc[QPT];
    #pragma unroll
    for (int u = 0; u < QPT; u++) acc[u] = pack2(0.0f, 0.0f);  // {se, sw}
    const float one = 1.0f;

    const int key0 = split * KEYS_PER_SPLIT;

    for (int t0 = 0; t0 < KEYS_PER_SPLIT; t0 += KTILE) {
        __syncthreads();
        const ulonglong2* src = reinterpret_cast<const ulonglong2*>(feats) + (key0 + t0) * 4;
        #pragma unroll
        for (int i = tid; i < KTILE * 4; i += QBLK) sk[i] = src[i];
        __syncthreads();

        #pragma unroll 2
        for (int j = 0; j < KTILE; j++) {
            ulonglong2 p0 = sk[4 * j + 0];
            ulonglong2 p1 = sk[4 * j + 1];
            ulonglong2 p2 = sk[4 * j + 2];
            ulonglong2 p3 = sk[4 * j + 3];

            u64 m[QPT];
            #pragma unroll
            for (int u = 0; u < QPT; u++) {
                // two parallel 4-deep FFMA2 chains per query
                u64 a0 = mul2(qp[u][0], p0.x);
                u64 a1 = mul2(qp[u][4], p2.x);
                a0 = fma2(qp[u][1], p0.y, a0);
                a1 = fma2(qp[u][5], p2.y, a1);
                a0 = fma2(qp[u][2], p1.x, a0);
                a1 = fma2(qp[u][6], p3.x, a1);
                a0 = fma2(qp[u][3], p1.y, a0);
                a1 = fma2(qp[u][7], p3.y, a1);
                m[u] = add2(a0, a1);
            }

            #pragma unroll
            for (int u = 0; u < QPT; u++) {
                float lo, hi;
                unpack2(m[u], lo, hi);
                float t = lo + hi;          // score in log2 units
                float e = ex2_approx(t);    // = exp(score)
                acc[u] = fma2(pack2(e, e), pack2(one, t), acc[u]);
            }
        }
    }

    #pragma unroll
    for (int u = 0; u < QPT; u++) {
        float se, sw;
        unpack2(acc[u], se, sw);
        g_se[split][qbase + u * QBLK] = se;
        g_sw[split][qbase + u * QBLK] = sw;
    }
}

// ---------------------------------------------------------------------------
// Kernel 2: per-point weight w = sigmoid(4*ln2 * sw/se), then block-local SOP
// partial  M_b = sum_i w_i^2 f_i f_i^T  over this block's 256 points.
// (topK=1 -> k=N -> all points kept; /k cancels in final L2-normalize.)
// ---------------------------------------------------------------------------
__global__ void __launch_bounds__(SOP_BLK) sop_kernel(const float* __restrict__ feats) {
    __shared__ float sf[SOP_BLK][DIM];
    __shared__ float sw2[SOP_BLK];

    const int tid = threadIdx.x;
    const int b   = blockIdx.x;
    const int p   = b * SOP_BLK + tid;

    float se = 0.0f, sw = 0.0f;
    #pragma unroll
    for (int s = 0; s < KSPLIT; s++) {
        se += g_se[s][p];
        sw += g_sw[s][p];
    }
    // cf = <ctx, f> = 4*ln2 * sw/se ; w = sigmoid(cf)
    const float c4ln2 = 4.0f * 0.6931471805599453f;
    float cf = c4ln2 * sw / se;
    float w = 1.0f / (1.0f + __expf(-cf));
    sw2[tid] = w * w;

    const float4* fp = reinterpret_cast<const float4*>(feats) + p * 4;
    float4 f0 = fp[0], f1 = fp[1], f2 = fp[2], f3 = fp[3];
    sf[tid][0]  = f0.x; sf[tid][1]  = f0.y; sf[tid][2]  = f0.z; sf[tid][3]  = f0.w;
    sf[tid][4]  = f1.x; sf[tid][5]  = f1.y; sf[tid][6]  = f1.z; sf[tid][7]  = f1.w;
    sf[tid][8]  = f2.x; sf[tid][9]  = f2.y; sf[tid][10] = f2.z; sf[tid][11] = f2.w;
    sf[tid][12] = f3.x; sf[tid][13] = f3.y; sf[tid][14] = f3.z; sf[tid][15] = f3.w;
    __syncthreads();

    // thread t owns entry (d, e) of the 16x16 outer-product sum
    const int d = tid >> 4;
    const int e = tid & 15;
    float acc = 0.0f;
    #pragma unroll 8
    for (int i = 0; i < SOP_BLK; i++) {
        acc = fmaf(sw2[i] * sf[i][d], sf[i][e], acc);
    }
    g_Mpart[b][tid] = acc;
}

// ---------------------------------------------------------------------------
// Kernel 3: reduce SOP partials, L2-normalize, write 256-float output.
// ---------------------------------------------------------------------------
__global__ void finalize_kernel(float* __restrict__ out) {
    __shared__ float red[256];
    const int t = threadIdx.x;

    float v = 0.0f;
    #pragma unroll 8
    for (int b = 0; b < SOP_BLOCKS; b++) v += g_Mpart[b][t];

    red[t] = v * v;
    __syncthreads();
    #pragma unroll
    for (int o = 128; o > 0; o >>= 1) {
        if (t < o) red[t] += red[t + o];
        __syncthreads();
    }
    float inv = 1.0f / sqrtf(red[0]);
    out[t] = v * inv;
}

// ---------------------------------------------------------------------------
extern "C" void kernel_launch(void* const* d_in, const int* in_sizes, int n_in,
                              void* d_out, int out_size) {
    const float* feats = (const float*)d_in[0];
    float* out = (float*)d_out;

    attn_kernel<<<KSPLIT * QTILES, QBLK>>>(feats);
    sop_kernel<<<SOP_BLOCKS, SOP_BLK>>>(feats);
    finalize_kernel<<<1, 256>>>(out);
}

// round 7
// speedup vs baseline: 3.1244x; 3.1244x over previous
#include <cuda_runtime.h>
#include <cuda_bf16.h>
#include <cstdint>

#define NPTS 12288
#define DIM 16
#define KSPLIT 6
#define QT_TILES 96                     // 12288/128 query tiles
#define TPB 256
#define KEYS_PER_SPLIT (NPTS / KSPLIT)  // 2048
#define KEYTILE 512
#define TILES (KEYS_PER_SPLIT / KEYTILE)// 4
#define SOP_BLK 256
#define SOP_BLOCKS (NPTS / SOP_BLK)     // 48

// ---- scratch (__device__ globals; no allocation allowed) ------------------
__device__ uint32_t g_qa[NPTS * 8];         // queries, bf16x2, pre-scaled by 0.25*log2(e)
__device__ uint32_t g_kb[NPTS * 8];         // keys, bf16x2, unscaled
__device__ float g_se[KSPLIT][NPTS];        // exp-sum partials
__device__ float g_sw[KSPLIT][NPTS];        // exp*score-sum partials (log2-units)
__device__ float g_Mpart[SOP_BLOCKS][256];  // per-block SOP partials

__device__ __forceinline__ float ex2_approx(float x) {
    float r; asm("ex2.approx.ftz.f32 %0, %1;" : "=f"(r) : "f"(x)); return r;
}

// ---------------------------------------------------------------------------
// Kernel 0: convert feats (f32) to bf16 row-major arrays.
// g_qa = feats * 0.25*log2(e)  (A operand; MMA output is score in log2 units)
// g_kb = feats                 (B operand)
// ---------------------------------------------------------------------------
__global__ void convert_kernel(const float* __restrict__ feats) {
    const int p = blockIdx.x * 256 + threadIdx.x;
    const float* f = feats + p * DIM;
    const float sc = 0.25f * 1.4426950408889634f;
    #pragma unroll
    for (int i = 0; i < 8; i++) {
        float x0 = f[2 * i], x1 = f[2 * i + 1];
        __nv_bfloat162 qa = __floats2bfloat162_rn(x0 * sc, x1 * sc);
        __nv_bfloat162 kb = __floats2bfloat162_rn(x0, x1);
        g_qa[p * 8 + i] = *reinterpret_cast<uint32_t*>(&qa);
        g_kb[p * 8 + i] = *reinterpret_cast<uint32_t*>(&kb);
    }
}

// ---------------------------------------------------------------------------
// Kernel 1: tensor-core attention row stats via warp-level mma.sync.
// Block = 256 thr = 8 warps; warp owns 16 queries (A fragment, loaded once).
// Loop: stage 512-key tile in smem (48B/key stride -> conflict-free B loads),
// then 64 MMAs (m16n8k16): scores for (16q x 8k) land in d0..d3 of each
// thread (rows g, g+8; 2 keys each). Epilogue per score: e = 2^t;
// se += e; sw += e*t. Final quad reduction via shfl.xor(1,2).
// Identity from R3: <ctx_q,f_q> = 4*ln2 * sw/se, so no ctx needed.
// ---------------------------------------------------------------------------
__global__ void __launch_bounds__(TPB, 4) attn_mma_kernel() {
    __shared__ uint32_t sk[KEYTILE * 12];   // 24 KB, 48B per key (12 words)

    const int tid  = threadIdx.x;
    const int warp = tid >> 5;
    const int lane = tid & 31;
    const int g    = lane >> 2;             // 0..7
    const int tig  = lane & 3;              // 0..3
    const int qt    = blockIdx.x % QT_TILES;
    const int split = blockIdx.x / QT_TILES;

    const int q0 = qt * 128 + warp * 16 + g;
    const int q1 = q0 + 8;

    // A fragment (row-major 16x16 bf16): rows g/g+8, cols 2tig..2tig+1, +8
    const uint32_t a0 = g_qa[q0 * 8 + tig];
    const uint32_t a1 = g_qa[q1 * 8 + tig];
    const uint32_t a2 = g_qa[q0 * 8 + tig + 4];
    const uint32_t a3 = g_qa[q1 * 8 + tig + 4];

    float se0 = 0.0f, se1 = 0.0f, sw0 = 0.0f, sw1 = 0.0f;

    const int key0 = split * KEYS_PER_SPLIT;

    for (int tile = 0; tile < TILES; tile++) {
        __syncthreads();
        // stage 512 keys: src float4 f covers key f/2, half f&1 (32B/key)
        {
            const float4* src = reinterpret_cast<const float4*>(g_kb)
                              + (key0 + tile * KEYTILE) * 2;
            float4* dst = reinterpret_cast<float4*>(sk);
            #pragma unroll
            for (int f = tid; f < KEYTILE * 2; f += TPB) {
                int key = f >> 1, half = f & 1;
                dst[key * 3 + half] = src[f];
            }
        }
        __syncthreads();

        #pragma unroll 4
        for (int j = 0; j < KEYTILE / 8; j++) {
            const int kb = j * 8 + g;       // this thread's B-fragment key
            uint32_t b0 = sk[kb * 12 + tig];
            uint32_t b1 = sk[kb * 12 + tig + 4];

            float d0, d1, d2, d3;
            asm volatile(
                "mma.sync.aligned.m16n8k16.row.col.f32.bf16.bf16.f32 "
                "{%0,%1,%2,%3}, {%4,%5,%6,%7}, {%8,%9}, {%10,%11,%12,%13};"
                : "=f"(d0), "=f"(d1), "=f"(d2), "=f"(d3)
                : "r"(a0), "r"(a1), "r"(a2), "r"(a3), "r"(b0), "r"(b1),
                  "f"(0.0f), "f"(0.0f), "f"(0.0f), "f"(0.0f));

            // d0,d1: row g (keys 2tig,2tig+1); d2,d3: row g+8
            float e;
            e = ex2_approx(d0); se0 += e; sw0 = fmaf(e, d0, sw0);
            e = ex2_approx(d1); se0 += e; sw0 = fmaf(e, d1, sw0);
            e = ex2_approx(d2); se1 += e; sw1 = fmaf(e, d2, sw1);
            e = ex2_approx(d3); se1 += e; sw1 = fmaf(e, d3, sw1);
        }
    }

    // reduce across the 4 threads of each row-quad (tids 4g..4g+3)
    se0 += __shfl_xor_sync(0xffffffffu, se0, 1);
    se0 += __shfl_xor_sync(0xffffffffu, se0, 2);
    se1 += __shfl_xor_sync(0xffffffffu, se1, 1);
    se1 += __shfl_xor_sync(0xffffffffu, se1, 2);
    sw0 += __shfl_xor_sync(0xffffffffu, sw0, 1);
    sw0 += __shfl_xor_sync(0xffffffffu, sw0, 2);
    sw1 += __shfl_xor_sync(0xffffffffu, sw1, 1);
    sw1 += __shfl_xor_sync(0xffffffffu, sw1, 2);

    if (tig == 0) {
        g_se[split][q0] = se0;
        g_sw[split][q0] = sw0;
        g_se[split][q1] = se1;
        g_sw[split][q1] = sw1;
    }
}

// ---------------------------------------------------------------------------
// Kernel 2: w = sigmoid(4*ln2 * sw/se); block-local SOP partial
// M_b = sum_i w_i^2 f_i f_i^T  (topK=1 -> all points; /k cancels in L2-norm).
// ---------------------------------------------------------------------------
__global__ void __launch_bounds__(SOP_BLK) sop_kernel(const float* __restrict__ feats) {
    __shared__ float sf[SOP_BLK][DIM];
    __shared__ float sw2[SOP_BLK];

    const int tid = threadIdx.x;
    const int b   = blockIdx.x;
    const int p   = b * SOP_BLK + tid;

    float se = 0.0f, sw = 0.0f;
    #pragma unroll
    for (int s = 0; s < KSPLIT; s++) {
        se += g_se[s][p];
        sw += g_sw[s][p];
    }
    const float c4ln2 = 4.0f * 0.6931471805599453f;
    float cf = c4ln2 * sw / se;
    float w = 1.0f / (1.0f + __expf(-cf));
    sw2[tid] = w * w;

    const float4* fp = reinterpret_cast<const float4*>(feats) + p * 4;
    float4 f0 = fp[0], f1 = fp[1], f2 = fp[2], f3 = fp[3];
    sf[tid][0]  = f0.x; sf[tid][1]  = f0.y; sf[tid][2]  = f0.z; sf[tid][3]  = f0.w;
    sf[tid][4]  = f1.x; sf[tid][5]  = f1.y; sf[tid][6]  = f1.z; sf[tid][7]  = f1.w;
    sf[tid][8]  = f2.x; sf[tid][9]  = f2.y; sf[tid][10] = f2.z; sf[tid][11] = f2.w;
    sf[tid][12] = f3.x; sf[tid][13] = f3.y; sf[tid][14] = f3.z; sf[tid][15] = f3.w;
    __syncthreads();

    const int d = tid >> 4;
    const int e = tid & 15;
    float acc = 0.0f;
    #pragma unroll 8
    for (int i = 0; i < SOP_BLK; i++) {
        acc = fmaf(sw2[i] * sf[i][d], sf[i][e], acc);
    }
    g_Mpart[b][tid] = acc;
}

// ---------------------------------------------------------------------------
// Kernel 3: reduce SOP partials, L2-normalize, write 256-float output.
// ---------------------------------------------------------------------------
__global__ void finalize_kernel(float* __restrict__ out) {
    __shared__ float red[256];
    const int t = threadIdx.x;

    float v = 0.0f;
    #pragma unroll 8
    for (int b = 0; b < SOP_BLOCKS; b++) v += g_Mpart[b][t];

    red[t] = v * v;
    __syncthreads();
    #pragma unroll
    for (int o = 128; o > 0; o >>= 1) {
        if (t < o) red[t] += red[t + o];
        __syncthreads();
    }
    float inv = 1.0f / sqrtf(red[0]);
    out[t] = v * inv;
}

// ---------------------------------------------------------------------------
extern "C" void kernel_launch(void* const* d_in, const int* in_sizes, int n_in,
                              void* d_out, int out_size) {
    const float* feats = (const float*)d_in[0];
    float* out = (float*)d_out;

    convert_kernel<<<NPTS / 256, 256>>>(feats);
    attn_mma_kernel<<<KSPLIT * QT_TILES, TPB>>>();
    sop_kernel<<<SOP_BLOCKS, SOP_BLK>>>(feats);
    finalize_kernel<<<1, 256>>>(out);
}